// round 1
// baseline (speedup 1.0000x reference)
#include <cuda_runtime.h>
#include <cuda_bf16.h>
#include <cstdint>

#define NUM_USERS 100000
#define NUM_ITEMS 50000
#define N_NODES   150000
#define EMBED_DIM 64
#define NNZ       4000000

// Node matrix as float4: 150000 * 16 float4 = 2,400,000 float4
#define N_VEC4    (N_NODES * (EMBED_DIM / 4))          // 2.4M
#define USER_VEC4 (NUM_USERS * (EMBED_DIM / 4))        // 1.6M

// Double-buffered node feature matrices (38.4 MB each) — static device scratch
__device__ float4 g_hA[N_VEC4];
__device__ float4 g_hB[N_VEC4];

// ---------------------------------------------------------------------------
// init: hA = concat(user_emb, item_emb); out = same; hB = 0
// ---------------------------------------------------------------------------
__global__ void init_kernel(const float4* __restrict__ u4,
                            const float4* __restrict__ i4,
                            float4* __restrict__ out4) {
    int f = blockIdx.x * blockDim.x + threadIdx.x;
    if (f >= N_VEC4) return;
    float4 v = (f < USER_VEC4) ? __ldg(u4 + f) : __ldg(i4 + (f - USER_VEC4));
    g_hA[f] = v;
    out4[f] = v;
    g_hB[f] = make_float4(0.f, 0.f, 0.f, 0.f);
}

// ---------------------------------------------------------------------------
// SpMM: y[rows[e]] += vals[e] * x[cols[e]]   (64-wide rows)
// 16 threads per edge, each handles one float4 (16 B). Gather is coalesced
// 256 B from L2-resident x; scatter is coalesced red.global.add.v4.f32.
// ---------------------------------------------------------------------------
__global__ void __launch_bounds__(256) spmm_kernel(
    const float4* __restrict__ x,   // [N_NODES*16] float4
    float4* __restrict__ y,         // [N_NODES*16] float4 (pre-zeroed)
    const float* __restrict__ vals,
    const int*   __restrict__ rows,
    const int*   __restrict__ cols) {
    long long tid = (long long)blockIdx.x * blockDim.x + threadIdx.x;
    if (tid >= (long long)NNZ * 16) return;
    int e = (int)(tid >> 4);
    int d = (int)(tid & 15);

    int   r = __ldg(rows + e);
    int   c = __ldg(cols + e);
    float v = __ldg(vals + e);

    float4 xv = __ldg(x + c * 16 + d);
    float4 p;
    p.x = v * xv.x; p.y = v * xv.y; p.z = v * xv.z; p.w = v * xv.w;

    float4* dst = y + r * 16 + d;
    asm volatile("red.global.add.v4.f32 [%0], {%1, %2, %3, %4};"
                 :: "l"(dst), "f"(p.x), "f"(p.y), "f"(p.z), "f"(p.w)
                 : "memory");
}

// ---------------------------------------------------------------------------
// acc += h_new ; h_zero = 0  (prepare next destination buffer)
// ---------------------------------------------------------------------------
__global__ void acc_zero_kernel(float4* __restrict__ acc,
                                const float4* __restrict__ h_new,
                                float4* __restrict__ h_zero) {
    int f = blockIdx.x * blockDim.x + threadIdx.x;
    if (f >= N_VEC4) return;
    float4 a = acc[f];
    float4 h = h_new[f];
    a.x += h.x; a.y += h.y; a.z += h.z; a.w += h.w;
    acc[f] = a;
    h_zero[f] = make_float4(0.f, 0.f, 0.f, 0.f);
}

// ---------------------------------------------------------------------------
// final: out = (out + h_last) * 0.25
// ---------------------------------------------------------------------------
__global__ void final_kernel(float4* __restrict__ out4,
                             const float4* __restrict__ h_last) {
    int f = blockIdx.x * blockDim.x + threadIdx.x;
    if (f >= N_VEC4) return;
    float4 a = out4[f];
    float4 h = h_last[f];
    a.x = (a.x + h.x) * 0.25f;
    a.y = (a.y + h.y) * 0.25f;
    a.z = (a.z + h.z) * 0.25f;
    a.w = (a.w + h.w) * 0.25f;
    out4[f] = a;
}

// ---------------------------------------------------------------------------
// Launch sequence (graph-capturable: kernels only)
// Inputs (metadata order): user_emb f32[100000,64], item_emb f32[50000,64],
//                          vals f32[4M], rows i32[4M], cols i32[4M]
// Output: f32[150000*64] = concat(users, items) of (sum over 4 terms)/4
// ---------------------------------------------------------------------------
extern "C" void kernel_launch(void* const* d_in, const int* in_sizes, int n_in,
                              void* d_out, int out_size) {
    const float4* u4   = (const float4*)d_in[0];
    const float4* i4   = (const float4*)d_in[1];
    const float*  vals = (const float*)d_in[2];
    const int*    rows = (const int*)d_in[3];
    const int*    cols = (const int*)d_in[4];
    float4* out4 = (float4*)d_out;

    float4* hA; cudaGetSymbolAddress((void**)&hA, g_hA);
    float4* hB; cudaGetSymbolAddress((void**)&hB, g_hB);

    const int TPB = 256;
    const int vec_blocks  = (N_VEC4 + TPB - 1) / TPB;
    const long long spmm_threads = (long long)NNZ * 16;
    const int spmm_blocks = (int)((spmm_threads + TPB - 1) / TPB);

    // h0 -> hA, out = h0, hB = 0
    init_kernel<<<vec_blocks, TPB>>>(u4, i4, out4);

    // layer 1: hB = A*hA ; out += hB ; hA = 0
    spmm_kernel<<<spmm_blocks, TPB>>>(hA, hB, vals, rows, cols);
    acc_zero_kernel<<<vec_blocks, TPB>>>(out4, hB, hA);

    // layer 2: hA = A*hB ; out += hA ; hB = 0
    spmm_kernel<<<spmm_blocks, TPB>>>(hB, hA, vals, rows, cols);
    acc_zero_kernel<<<vec_blocks, TPB>>>(out4, hA, hB);

    // layer 3: hB = A*hA ; out = (out + hB)/4
    spmm_kernel<<<spmm_blocks, TPB>>>(hA, hB, vals, rows, cols);
    final_kernel<<<vec_blocks, TPB>>>(out4, hB);
}

// round 2
// speedup vs baseline: 1.3203x; 1.3203x over previous
#include <cuda_runtime.h>
#include <cuda_bf16.h>
#include <cstdint>

#define NUM_USERS 100000
#define NUM_ITEMS 50000
#define N_NODES   150000
#define EMBED_DIM 64
#define NNZ       4000000

// Node matrix as float4: 150000 * 16 float4 = 2,400,000 float4
#define N_VEC4    (N_NODES * (EMBED_DIM / 4))          // 2.4M
#define USER_VEC4 (NUM_USERS * (EMBED_DIM / 4))        // 1.6M

#define EPB 256            // edges per block (staged in smem)
#define TPB 256

// Double-buffered node feature matrices (38.4 MB each) — static device scratch
__device__ float4 g_hA[N_VEC4];
__device__ float4 g_hB[N_VEC4];

// ---------------------------------------------------------------------------
// init: hA = concat(user_emb, item_emb); out = same; hB = 0
// ---------------------------------------------------------------------------
__global__ void init_kernel(const float4* __restrict__ u4,
                            const float4* __restrict__ i4,
                            float4* __restrict__ out4) {
    int f = blockIdx.x * blockDim.x + threadIdx.x;
    if (f >= N_VEC4) return;
    float4 v = (f < USER_VEC4) ? __ldg(u4 + f) : __ldg(i4 + (f - USER_VEC4));
    g_hA[f] = v;
    out4[f] = v;
    g_hB[f] = make_float4(0.f, 0.f, 0.f, 0.f);
}

// ---------------------------------------------------------------------------
// SpMM: y[rows[e]] += vals[e] * x[cols[e]]   (64-wide rows)
//
// Block stages EPB edges' (row, col, val) in smem with one coalesced load,
// then processes them with 16 threads/edge × 16 iterations. Edge metadata
// is read via broadcast LDS (2 distinct addrs per warp instr) instead of
// 16-way-redundant LDG — cuts L1tex instruction traffic ~60%.
// Per work-item: 1 LDG.128 gather (L2-resident x) + 1 RED.128 scatter.
// ---------------------------------------------------------------------------
__global__ void __launch_bounds__(TPB) spmm_kernel(
    const float4* __restrict__ x,   // [N_NODES*16] float4
    float4* __restrict__ y,         // [N_NODES*16] float4 (pre-zeroed)
    const float* __restrict__ vals,
    const int*   __restrict__ rows,
    const int*   __restrict__ cols) {
    __shared__ int   srow[EPB];
    __shared__ int   scol[EPB];
    __shared__ float sval[EPB];

    const int t  = threadIdx.x;
    const int e0 = blockIdx.x * EPB;

    // coalesced metadata stage (EPB == TPB)
    srow[t] = __ldg(rows + e0 + t);
    scol[t] = __ldg(cols + e0 + t);
    sval[t] = __ldg(vals + e0 + t);
    __syncthreads();

    const int d    = t & 15;        // float4 slot within the 64-wide row
    const int slot = t >> 4;        // edge slot within an iteration (0..15)

    #pragma unroll
    for (int k = 0; k < EPB / 16; k++) {
        int   el = slot + k * 16;
        int   r  = srow[el];
        int   c  = scol[el];
        float v  = sval[el];

        float4 xv = __ldg(x + c * 16 + d);
        float4 p;
        p.x = v * xv.x; p.y = v * xv.y; p.z = v * xv.z; p.w = v * xv.w;

        float4* dst = y + r * 16 + d;
        asm volatile("red.global.add.v4.f32 [%0], {%1, %2, %3, %4};"
                     :: "l"(dst), "f"(p.x), "f"(p.y), "f"(p.z), "f"(p.w)
                     : "memory");
    }
}

// ---------------------------------------------------------------------------
// acc += h_new ; h_zero = 0  (prepare next destination buffer)
// ---------------------------------------------------------------------------
__global__ void acc_zero_kernel(float4* __restrict__ acc,
                                const float4* __restrict__ h_new,
                                float4* __restrict__ h_zero) {
    int f = blockIdx.x * blockDim.x + threadIdx.x;
    if (f >= N_VEC4) return;
    float4 a = acc[f];
    float4 h = h_new[f];
    a.x += h.x; a.y += h.y; a.z += h.z; a.w += h.w;
    acc[f] = a;
    h_zero[f] = make_float4(0.f, 0.f, 0.f, 0.f);
}

// ---------------------------------------------------------------------------
// final: out = (out + h_last) * 0.25
// ---------------------------------------------------------------------------
__global__ void final_kernel(float4* __restrict__ out4,
                             const float4* __restrict__ h_last) {
    int f = blockIdx.x * blockDim.x + threadIdx.x;
    if (f >= N_VEC4) return;
    float4 a = out4[f];
    float4 h = h_last[f];
    a.x = (a.x + h.x) * 0.25f;
    a.y = (a.y + h.y) * 0.25f;
    a.z = (a.z + h.z) * 0.25f;
    a.w = (a.w + h.w) * 0.25f;
    out4[f] = a;
}

// ---------------------------------------------------------------------------
// Launch sequence (graph-capturable: kernels only)
// Inputs (metadata order): user_emb f32[100000,64], item_emb f32[50000,64],
//                          vals f32[4M], rows i32[4M], cols i32[4M]
// ---------------------------------------------------------------------------
extern "C" void kernel_launch(void* const* d_in, const int* in_sizes, int n_in,
                              void* d_out, int out_size) {
    const float4* u4   = (const float4*)d_in[0];
    const float4* i4   = (const float4*)d_in[1];
    const float*  vals = (const float*)d_in[2];
    const int*    rows = (const int*)d_in[3];
    const int*    cols = (const int*)d_in[4];
    float4* out4 = (float4*)d_out;

    float4* hA; cudaGetSymbolAddress((void**)&hA, g_hA);
    float4* hB; cudaGetSymbolAddress((void**)&hB, g_hB);

    const int vec_blocks  = (N_VEC4 + TPB - 1) / TPB;
    const int spmm_blocks = NNZ / EPB;   // 4M % 256 == 0

    // h0 -> hA, out = h0, hB = 0
    init_kernel<<<vec_blocks, TPB>>>(u4, i4, out4);

    // layer 1: hB = A*hA ; out += hB ; hA = 0
    spmm_kernel<<<spmm_blocks, TPB>>>(hA, hB, vals, rows, cols);
    acc_zero_kernel<<<vec_blocks, TPB>>>(out4, hB, hA);

    // layer 2: hA = A*hB ; out += hA ; hB = 0
    spmm_kernel<<<spmm_blocks, TPB>>>(hB, hA, vals, rows, cols);
    acc_zero_kernel<<<vec_blocks, TPB>>>(out4, hA, hB);

    // layer 3: hB = A*hA ; out = (out + hB)/4
    spmm_kernel<<<spmm_blocks, TPB>>>(hA, hB, vals, rows, cols);
    final_kernel<<<vec_blocks, TPB>>>(out4, hB);
}

// round 3
// speedup vs baseline: 1.4258x; 1.0799x over previous
#include <cuda_runtime.h>
#include <cuda_bf16.h>
#include <cstdint>

#define NUM_USERS 100000
#define NUM_ITEMS 50000
#define N_NODES   150000
#define EMBED_DIM 64
#define NNZ       4000000

#define N_VEC4    (N_NODES * (EMBED_DIM / 4))          // 2.4M float4
#define USER_VEC4 (NUM_USERS * (EMBED_DIM / 4))        // 1.6M

#define EPB 256            // edges per block (staged in smem)
#define TPB 256

// bf16 gather matrix: row = 64 bf16 = 16 uint2 (128B rows) — 19.2 MB
__device__ uint2  g_xb[N_NODES * 16];
// fp32 accumulation target for the SpMM scatter — 38.4 MB
__device__ float4 g_yf[N_VEC4];

static __device__ __forceinline__ uint2 pack_bf16x4(float4 v) {
    __nv_bfloat162 lo = __floats2bfloat162_rn(v.x, v.y);
    __nv_bfloat162 hi = __floats2bfloat162_rn(v.z, v.w);
    uint2 p;
    p.x = *reinterpret_cast<unsigned*>(&lo);
    p.y = *reinterpret_cast<unsigned*>(&hi);
    return p;
}

// ---------------------------------------------------------------------------
// init: out = h0 = concat(user, item); xb = bf16(h0); yf = 0
// ---------------------------------------------------------------------------
__global__ void init_kernel(const float4* __restrict__ u4,
                            const float4* __restrict__ i4,
                            float4* __restrict__ out4) {
    int f = blockIdx.x * blockDim.x + threadIdx.x;
    if (f >= N_VEC4) return;
    float4 v = (f < USER_VEC4) ? __ldg(u4 + f) : __ldg(i4 + (f - USER_VEC4));
    out4[f]  = v;
    g_xb[f]  = pack_bf16x4(v);
    g_yf[f]  = make_float4(0.f, 0.f, 0.f, 0.f);
}

// ---------------------------------------------------------------------------
// SpMM: yf[rows[e]] += vals[e] * bf16_gather(xb[cols[e]])
// 16 threads/edge: each gathers 8B (4 bf16), converts to fp32, multiplies,
// scatters 16B via red.global.add.v4.f32. Edge metadata via smem broadcast.
// Per 2-edge warp-iter: 2 gather wavefronts + 4 scatter wavefronts.
// ---------------------------------------------------------------------------
__global__ void __launch_bounds__(TPB) spmm_kernel(
    const uint2* __restrict__ xb,   // [N_NODES*16] uint2 (bf16x4)
    float4* __restrict__ yf,        // [N_NODES*16] float4 (pre-zeroed)
    const float* __restrict__ vals,
    const int*   __restrict__ rows,
    const int*   __restrict__ cols) {
    __shared__ int   srow[EPB];
    __shared__ int   scol[EPB];
    __shared__ float sval[EPB];

    const int t  = threadIdx.x;
    const int e0 = blockIdx.x * EPB;

    srow[t] = __ldg(rows + e0 + t);
    scol[t] = __ldg(cols + e0 + t);
    sval[t] = __ldg(vals + e0 + t);
    __syncthreads();

    const int d    = t & 15;        // uint2 slot within the 128B bf16 row
    const int slot = t >> 4;        // edge slot within an iteration (0..15)

    #pragma unroll
    for (int k = 0; k < EPB / 16; k++) {
        int   el = slot + k * 16;
        int   r  = srow[el];
        int   c  = scol[el];
        float v  = sval[el];

        uint2 q = __ldg(xb + c * 16 + d);
        __nv_bfloat162 lo = *reinterpret_cast<__nv_bfloat162*>(&q.x);
        __nv_bfloat162 hi = *reinterpret_cast<__nv_bfloat162*>(&q.y);
        float2 flo = __bfloat1622float2(lo);
        float2 fhi = __bfloat1622float2(hi);

        float4 p;
        p.x = v * flo.x; p.y = v * flo.y;
        p.z = v * fhi.x; p.w = v * fhi.y;

        float4* dst = yf + r * 16 + d;
        asm volatile("red.global.add.v4.f32 [%0], {%1, %2, %3, %4};"
                     :: "l"(dst), "f"(p.x), "f"(p.y), "f"(p.z), "f"(p.w)
                     : "memory");
    }
}

// ---------------------------------------------------------------------------
// acc += h ; xb = bf16(h) ; yf = 0   (prepare next layer)
// ---------------------------------------------------------------------------
__global__ void acc_convert_kernel(float4* __restrict__ acc) {
    int f = blockIdx.x * blockDim.x + threadIdx.x;
    if (f >= N_VEC4) return;
    float4 h = g_yf[f];
    float4 a = acc[f];
    a.x += h.x; a.y += h.y; a.z += h.z; a.w += h.w;
    acc[f] = a;
    g_xb[f] = pack_bf16x4(h);
    g_yf[f] = make_float4(0.f, 0.f, 0.f, 0.f);
}

// ---------------------------------------------------------------------------
// final: out = (out + h_last) * 0.25
// ---------------------------------------------------------------------------
__global__ void final_kernel(float4* __restrict__ out4) {
    int f = blockIdx.x * blockDim.x + threadIdx.x;
    if (f >= N_VEC4) return;
    float4 a = out4[f];
    float4 h = g_yf[f];
    a.x = (a.x + h.x) * 0.25f;
    a.y = (a.y + h.y) * 0.25f;
    a.z = (a.z + h.z) * 0.25f;
    a.w = (a.w + h.w) * 0.25f;
    out4[f] = a;
}

// ---------------------------------------------------------------------------
// Launch sequence (graph-capturable: kernels only)
// ---------------------------------------------------------------------------
extern "C" void kernel_launch(void* const* d_in, const int* in_sizes, int n_in,
                              void* d_out, int out_size) {
    const float4* u4   = (const float4*)d_in[0];
    const float4* i4   = (const float4*)d_in[1];
    const float*  vals = (const float*)d_in[2];
    const int*    rows = (const int*)d_in[3];
    const int*    cols = (const int*)d_in[4];
    float4* out4 = (float4*)d_out;

    uint2*  xb; cudaGetSymbolAddress((void**)&xb, g_xb);
    float4* yf; cudaGetSymbolAddress((void**)&yf, g_yf);

    const int vec_blocks  = (N_VEC4 + TPB - 1) / TPB;
    const int spmm_blocks = NNZ / EPB;   // 4M % 256 == 0

    // out = h0, xb = bf16(h0), yf = 0
    init_kernel<<<vec_blocks, TPB>>>(u4, i4, out4);

    // layer 1: yf = A*h0 ; out += yf ; xb = bf16(yf) ; yf = 0
    spmm_kernel<<<spmm_blocks, TPB>>>(xb, yf, vals, rows, cols);
    acc_convert_kernel<<<vec_blocks, TPB>>>(out4);

    // layer 2
    spmm_kernel<<<spmm_blocks, TPB>>>(xb, yf, vals, rows, cols);
    acc_convert_kernel<<<vec_blocks, TPB>>>(out4);

    // layer 3: yf = A*h2 ; out = (out + yf)/4
    spmm_kernel<<<spmm_blocks, TPB>>>(xb, yf, vals, rows, cols);
    final_kernel<<<vec_blocks, TPB>>>(out4);
}

// round 4
// speedup vs baseline: 2.2395x; 1.5707x over previous
#include <cuda_runtime.h>
#include <cuda_bf16.h>
#include <cuda_fp16.h>
#include <cstdint>

#define NUM_USERS 100000
#define NUM_ITEMS 50000
#define N_NODES   150000
#define EMBED_DIM 64
#define NNZ       4000000

#define N_VEC8    (N_NODES * (EMBED_DIM / 8))   // 1.2M  (8-dim granules)
#define USER_F4   (NUM_USERS * (EMBED_DIM / 4)) // 1.6M  (float4 units)

#define EPB 256
#define TPB 256

// bf16 gather matrix: 64 bf16 per row = 8 uint4 (128B rows) — 19.2 MB
__device__ uint4 g_xb[N_VEC8];
// fp16 accumulation target: 64 half per row = 8 uint4 — 19.2 MB
__device__ uint4 g_yh[N_VEC8];

static __device__ __forceinline__ unsigned pack_bf2(float a, float b) {
    __nv_bfloat162 h = __floats2bfloat162_rn(a, b);
    return *reinterpret_cast<unsigned*>(&h);
}
static __device__ __forceinline__ unsigned pack_h2(float a, float b) {
    __half2 h = __floats2half2_rn(a, b);
    return *reinterpret_cast<unsigned*>(&h);
}
static __device__ __forceinline__ float2 unpack_bf2(unsigned u) {
    return __bfloat1622float2(*reinterpret_cast<__nv_bfloat162*>(&u));
}
static __device__ __forceinline__ float2 unpack_h2(unsigned u) {
    return __half22float2(*reinterpret_cast<__half2*>(&u));
}

// ---------------------------------------------------------------------------
// init: out = h0 = concat(user, item); xb = bf16(h0); yh = 0
// One thread per 8-dim granule (two float4 loads/stores).
// ---------------------------------------------------------------------------
__global__ void init_kernel(const float4* __restrict__ u4,
                            const float4* __restrict__ i4,
                            float4* __restrict__ out4) {
    int f = blockIdx.x * blockDim.x + threadIdx.x;
    if (f >= N_VEC8) return;
    int f2 = f * 2;
    float4 a, b;
    if (f2 < USER_F4) { a = __ldg(u4 + f2);           b = __ldg(u4 + f2 + 1); }
    else              { a = __ldg(i4 + f2 - USER_F4); b = __ldg(i4 + f2 - USER_F4 + 1); }
    out4[f2]     = a;
    out4[f2 + 1] = b;
    uint4 p;
    p.x = pack_bf2(a.x, a.y); p.y = pack_bf2(a.z, a.w);
    p.z = pack_bf2(b.x, b.y); p.w = pack_bf2(b.z, b.w);
    g_xb[f] = p;
    g_yh[f] = make_uint4(0u, 0u, 0u, 0u);
}

// ---------------------------------------------------------------------------
// SpMM: yh[rows[e]] += f16( vals[e] * bf16_gather(xb[cols[e]]) )
// 8 threads/edge: thread d handles dims [8d, 8d+8): 16B bf16 gather,
// fp32 multiply, 16B red.global.add.noftz.v4.f16x2 scatter.
// Per edge: 1 gather wavefront + 1 scatter wavefront (was 1 + 2).
// ---------------------------------------------------------------------------
__global__ void __launch_bounds__(TPB) spmm_kernel(
    const uint4* __restrict__ xb,   // [N_VEC8] bf16x8
    __half* __restrict__ yh,        // [N_NODES*64] f16 (pre-zeroed)
    const float* __restrict__ vals,
    const int*   __restrict__ rows,
    const int*   __restrict__ cols) {
    __shared__ int   srow[EPB];
    __shared__ int   scol[EPB];
    __shared__ float sval[EPB];

    const int t  = threadIdx.x;
    const int e0 = blockIdx.x * EPB;

    srow[t] = __ldg(rows + e0 + t);
    scol[t] = __ldg(cols + e0 + t);
    sval[t] = __ldg(vals + e0 + t);
    __syncthreads();

    const int d    = t & 7;         // 8-dim granule within the row (0..7)
    const int slot = t >> 3;        // edge slot within an iteration (0..31)

    #pragma unroll
    for (int k = 0; k < EPB / 32; k++) {
        int   el = slot + k * 32;
        int   r  = srow[el];
        int   c  = scol[el];
        float v  = sval[el];

        uint4 q = __ldg(xb + c * 8 + d);
        float2 f0 = unpack_bf2(q.x);
        float2 f1 = unpack_bf2(q.y);
        float2 f2 = unpack_bf2(q.z);
        float2 f3 = unpack_bf2(q.w);

        unsigned h0 = pack_h2(v * f0.x, v * f0.y);
        unsigned h1 = pack_h2(v * f1.x, v * f1.y);
        unsigned h2 = pack_h2(v * f2.x, v * f2.y);
        unsigned h3 = pack_h2(v * f3.x, v * f3.y);

        __half* dst = yh + r * 64 + d * 8;   // 16B aligned
        asm volatile("red.global.add.noftz.v4.f16x2 [%0], {%1, %2, %3, %4};"
                     :: "l"(dst), "r"(h0), "r"(h1), "r"(h2), "r"(h3)
                     : "memory");
    }
}

// ---------------------------------------------------------------------------
// acc += h(f16) ; xb = bf16(h) ; yh = 0
// ---------------------------------------------------------------------------
__global__ void acc_convert_kernel(float4* __restrict__ acc) {
    int f = blockIdx.x * blockDim.x + threadIdx.x;
    if (f >= N_VEC8) return;
    uint4 q = g_yh[f];
    float2 f0 = unpack_h2(q.x);
    float2 f1 = unpack_h2(q.y);
    float2 f2 = unpack_h2(q.z);
    float2 f3 = unpack_h2(q.w);

    int f2i = f * 2;
    float4 a = acc[f2i], b = acc[f2i + 1];
    a.x += f0.x; a.y += f0.y; a.z += f1.x; a.w += f1.y;
    b.x += f2.x; b.y += f2.y; b.z += f3.x; b.w += f3.y;
    acc[f2i] = a; acc[f2i + 1] = b;

    uint4 p;
    p.x = pack_bf2(f0.x, f0.y); p.y = pack_bf2(f1.x, f1.y);
    p.z = pack_bf2(f2.x, f2.y); p.w = pack_bf2(f3.x, f3.y);
    g_xb[f] = p;
    g_yh[f] = make_uint4(0u, 0u, 0u, 0u);
}

// ---------------------------------------------------------------------------
// final: out = (out + h_last) * 0.25
// ---------------------------------------------------------------------------
__global__ void final_kernel(float4* __restrict__ out4) {
    int f = blockIdx.x * blockDim.x + threadIdx.x;
    if (f >= N_VEC8) return;
    uint4 q = g_yh[f];
    float2 f0 = unpack_h2(q.x);
    float2 f1 = unpack_h2(q.y);
    float2 f2 = unpack_h2(q.z);
    float2 f3 = unpack_h2(q.w);

    int f2i = f * 2;
    float4 a = out4[f2i], b = out4[f2i + 1];
    a.x = (a.x + f0.x) * 0.25f; a.y = (a.y + f0.y) * 0.25f;
    a.z = (a.z + f1.x) * 0.25f; a.w = (a.w + f1.y) * 0.25f;
    b.x = (b.x + f2.x) * 0.25f; b.y = (b.y + f2.y) * 0.25f;
    b.z = (b.z + f3.x) * 0.25f; b.w = (b.w + f3.y) * 0.25f;
    out4[f2i] = a; out4[f2i + 1] = b;
}

// ---------------------------------------------------------------------------
// Launch sequence (graph-capturable: kernels only)
// ---------------------------------------------------------------------------
extern "C" void kernel_launch(void* const* d_in, const int* in_sizes, int n_in,
                              void* d_out, int out_size) {
    const float4* u4   = (const float4*)d_in[0];
    const float4* i4   = (const float4*)d_in[1];
    const float*  vals = (const float*)d_in[2];
    const int*    rows = (const int*)d_in[3];
    const int*    cols = (const int*)d_in[4];
    float4* out4 = (float4*)d_out;

    uint4*  xb; cudaGetSymbolAddress((void**)&xb, g_xb);
    uint4*  yh; cudaGetSymbolAddress((void**)&yh, g_yh);

    const int vec_blocks  = (N_VEC8 + TPB - 1) / TPB;
    const int spmm_blocks = NNZ / EPB;

    init_kernel<<<vec_blocks, TPB>>>(u4, i4, out4);

    spmm_kernel<<<spmm_blocks, TPB>>>(xb, (__half*)yh, vals, rows, cols);
    acc_convert_kernel<<<vec_blocks, TPB>>>(out4);

    spmm_kernel<<<spmm_blocks, TPB>>>(xb, (__half*)yh, vals, rows, cols);
    acc_convert_kernel<<<vec_blocks, TPB>>>(out4);

    spmm_kernel<<<spmm_blocks, TPB>>>(xb, (__half*)yh, vals, rows, cols);
    final_kernel<<<vec_blocks, TPB>>>(out4);
}